// round 1
// baseline (speedup 1.0000x reference)
#include <cuda_runtime.h>
#include <cstdint>

// Problem constants
#define BATCH   1024
#define VOCAB   100000
#define DIM     128
#define NSEG    3
#define NBINS   4096          // top-12 bits of monotone key
#define HOTCAP  3072          // candidate buffer (expected ~1600 for N(0,1))
#define NTHREADS 1024
#define CUT0 100
#define CUT1 500
#define CUT2 1000

// Precomputed rerank_hidden[seg][row][d]
__device__ float g_rh[NSEG * BATCH * DIM];

// ---------------------------------------------------------------------------
// Kernel 1: rerank_hidden = hidden @ W[seg]^T + b[seg]
// grid (BATCH, NSEG), 128 threads; thread d computes output dim d.
// ---------------------------------------------------------------------------
__global__ void rh_kernel(const float* __restrict__ hidden,
                          const float* __restrict__ W,
                          const float* __restrict__ bias)
{
    int row = blockIdx.x;
    int seg = blockIdx.y;
    int d   = threadIdx.x;
    __shared__ float h[DIM];
    h[d] = hidden[row * DIM + d];
    __syncthreads();
    const float* w = W + (size_t)seg * DIM * DIM + (size_t)d * DIM;
    float s = bias[seg * DIM + d];
#pragma unroll 8
    for (int e = 0; e < DIM; e++) s += h[e] * w[e];
    g_rh[(size_t)seg * BATCH * DIM + (size_t)row * DIM + d] = s;
}

// Monotone mapping: float -> uint32 preserving order
__device__ __forceinline__ unsigned mono(float f) {
    unsigned u = __float_as_uint(f);
    return (u & 0x80000000u) ? ~u : (u | 0x80000000u);
}

// ---------------------------------------------------------------------------
// Kernel 2: per-row top-1000 selection + rerank + scatter. One CTA per row.
// ---------------------------------------------------------------------------
__global__ void __launch_bounds__(NTHREADS)
rerank_kernel(const float* __restrict__ logits,
              const float* __restrict__ emb,
              float* __restrict__ out)
{
    __shared__ unsigned long long hot[HOTCAP];   // (mono<<32)|~idx
    __shared__ unsigned hist[NBINS];
    __shared__ unsigned scanbuf[NTHREADS];
    __shared__ float rh[NSEG * DIM];
    __shared__ unsigned long long Tkey[3];       // threshold keys for ranks 100/500/1000
    __shared__ int s_bin[3];
    __shared__ int s_rank[3];                    // residual rank within bin (1-indexed)
    __shared__ int s_nhot;

    const int row = blockIdx.x;
    const int tid = threadIdx.x;

    // init
    for (int i = tid; i < NBINS; i += NTHREADS) hist[i] = 0u;
    if (tid < NSEG * DIM) {
        int seg = tid >> 7, d = tid & 127;
        rh[tid] = g_rh[(size_t)seg * BATCH * DIM + (size_t)row * DIM + d];
    }
    if (tid == 0) s_nhot = 0;
    __syncthreads();

    const float4* row4 = (const float4*)(logits + (size_t)row * VOCAB);
    float4*       out4 = (float4*)(out + (size_t)row * VOCAB);
    const int NV4 = VOCAB / 4;   // 25000

    // ---------------- Pass 1: copy out + histogram ----------------
    for (int i = tid; i < NV4; i += NTHREADS) {
        float4 v = row4[i];
        __stcs(&out4[i], v);     // streaming store: don't pollute L2
        atomicAdd(&hist[mono(v.x) >> 20], 1u);
        atomicAdd(&hist[mono(v.y) >> 20], 1u);
        atomicAdd(&hist[mono(v.z) >> 20], 1u);
        atomicAdd(&hist[mono(v.w) >> 20], 1u);
    }
    __syncthreads();

    // ---------------- Suffix scan: locate bins for ranks 100/500/1000 ----------
    // thread t owns descending-rank chunk of 4 bins: bins 4095-4t .. 4095-4t-3
    unsigned c0 = hist[4095 - 4 * tid];
    unsigned c1 = hist[4095 - 4 * tid - 1];
    unsigned c2 = hist[4095 - 4 * tid - 2];
    unsigned c3 = hist[4095 - 4 * tid - 3];
    unsigned chunk = c0 + c1 + c2 + c3;
    scanbuf[tid] = chunk;
    __syncthreads();
    // Hillis-Steele inclusive scan over 1024 entries
    for (int off = 1; off < NTHREADS; off <<= 1) {
        unsigned v = scanbuf[tid];
        unsigned a = (tid >= off) ? scanbuf[tid - off] : 0u;
        __syncthreads();
        scanbuf[tid] = v + a;
        __syncthreads();
    }
    unsigned incl = scanbuf[tid];
    unsigned excl = incl - chunk;
    const unsigned Ks[3] = {CUT0, CUT1, CUT2};
#pragma unroll
    for (int kk = 0; kk < 3; kk++) {
        unsigned K = Ks[kk];
        if (excl < K && K <= incl) {
            unsigned c = excl;
            unsigned cc[4] = {c0, c1, c2, c3};
#pragma unroll
            for (int j = 0; j < 4; j++) {
                unsigned h = cc[j];
                if (c < K && K <= c + h) {
                    s_bin[kk]  = 4095 - 4 * tid - j;
                    s_rank[kk] = (int)(K - c);      // 1-indexed rank within bin
                    break;
                }
                c += h;
            }
        }
    }
    __syncthreads();
    const int b100 = s_bin[0], b500 = s_bin[1], b1000 = s_bin[2];

    // ---------------- Pass 2: collect candidates (bin >= b1000) ----------------
    for (int i = tid; i < NV4; i += NTHREADS) {
        float4 v = row4[i];
        unsigned m;
        int idx4 = 4 * i;
        m = mono(v.x);
        if ((int)(m >> 20) >= b1000) {
            int p = atomicAdd(&s_nhot, 1);
            if (p < HOTCAP) hot[p] = ((unsigned long long)m << 32) | (unsigned)(~(idx4 + 0));
        }
        m = mono(v.y);
        if ((int)(m >> 20) >= b1000) {
            int p = atomicAdd(&s_nhot, 1);
            if (p < HOTCAP) hot[p] = ((unsigned long long)m << 32) | (unsigned)(~(idx4 + 1));
        }
        m = mono(v.z);
        if ((int)(m >> 20) >= b1000) {
            int p = atomicAdd(&s_nhot, 1);
            if (p < HOTCAP) hot[p] = ((unsigned long long)m << 32) | (unsigned)(~(idx4 + 2));
        }
        m = mono(v.w);
        if ((int)(m >> 20) >= b1000) {
            int p = atomicAdd(&s_nhot, 1);
            if (p < HOTCAP) hot[p] = ((unsigned long long)m << 32) | (unsigned)(~(idx4 + 3));
        }
    }
    __syncthreads();
    const int nhot = (s_nhot < HOTCAP) ? s_nhot : HOTCAP;

    // ---------------- Exact threshold keys via within-bin count-greater --------
    for (int i = tid; i < nhot; i += NTHREADS) {
        unsigned long long k = hot[i];
        int bin = (int)(k >> 52);
        bool m0 = (bin == b100), m1 = (bin == b500), m2 = (bin == b1000);
        if (m0 | m1 | m2) {
            int cnt = 0;
            for (int j = 0; j < nhot; j++) {
                unsigned long long kj = hot[j];
                if ((int)(kj >> 52) == bin && kj > k) cnt++;
            }
            int r = cnt + 1;
            if (m0 && r == s_rank[0]) Tkey[0] = k;
            if (m1 && r == s_rank[1]) Tkey[1] = k;
            if (m2 && r == s_rank[2]) Tkey[2] = k;
        }
    }
    __syncthreads();
    const unsigned long long T0 = Tkey[0], T1 = Tkey[1], T2 = Tkey[2];

    // ---------------- Dot phase: warp per top-k element ----------------
    const int wid = tid >> 5, lane = tid & 31;
    const float4* emb4 = (const float4*)emb;
    const float4* rh4  = (const float4*)rh;
    float* outrow = out + (size_t)row * VOCAB;
    for (int s = wid; s < nhot; s += (NTHREADS / 32)) {
        unsigned long long k = hot[s];
        if (k < T2) continue;                       // not in top-1000
        int seg = (k >= T0) ? 0 : ((k >= T1) ? 1 : 2);
        unsigned idx = ~(unsigned)k;                // recover column index
        float4 e = emb4[(size_t)idx * (DIM / 4) + lane];
        float4 r = rh4[seg * (DIM / 4) + lane];
        float p = e.x * r.x + e.y * r.y + e.z * r.z + e.w * r.w;
        p += __shfl_xor_sync(0xFFFFFFFFu, p, 16);
        p += __shfl_xor_sync(0xFFFFFFFFu, p, 8);
        p += __shfl_xor_sync(0xFFFFFFFFu, p, 4);
        p += __shfl_xor_sync(0xFFFFFFFFu, p, 2);
        p += __shfl_xor_sync(0xFFFFFFFFu, p, 1);
        if (lane == 0) outrow[idx] = p;
    }
}

// ---------------------------------------------------------------------------
// kernel_launch: map inputs by element count (robust to ordering), launch.
// ---------------------------------------------------------------------------
extern "C" void kernel_launch(void* const* d_in, const int* in_sizes, int n_in,
                              void* d_out, int out_size)
{
    const float* hidden = nullptr;
    const float* logits = nullptr;
    const float* emb    = nullptr;
    const float* W      = nullptr;
    const float* bias   = nullptr;
    for (int i = 0; i < n_in; i++) {
        switch (in_sizes[i]) {
            case BATCH * DIM:          hidden = (const float*)d_in[i]; break;  // 131072
            case BATCH * VOCAB:        logits = (const float*)d_in[i]; break;  // 102400000
            case VOCAB * DIM:          emb    = (const float*)d_in[i]; break;  // 12800000
            case NSEG * DIM * DIM:     W      = (const float*)d_in[i]; break;  // 49152
            case NSEG * DIM:           bias   = (const float*)d_in[i]; break;  // 384
        }
    }
    float* out = (float*)d_out;

    rh_kernel<<<dim3(BATCH, NSEG), DIM>>>(hidden, W, bias);
    rerank_kernel<<<BATCH, NTHREADS>>>(logits, emb, out);
}

// round 2
// speedup vs baseline: 1.1809x; 1.1809x over previous
#include <cuda_runtime.h>
#include <cstdint>

#define BATCH    1024
#define VOCAB    100000
#define DIM      128
#define NSEG     3
#define NBINS    4096
#define HOTCAP   3072
#define NTHREADS 1024
#define CUT0 100
#define CUT1 500
#define CUT2 1000
#define TGUESS 2.0f          // candidate threshold; rank-1000 of 100k N(0,1) ~ 2.33

__device__ float g_rh[NSEG * BATCH * DIM];

// ---------------------------------------------------------------------------
// Kernel 1: rerank_hidden = hidden @ W[seg]^T + b[seg]
// ---------------------------------------------------------------------------
__global__ void rh_kernel(const float* __restrict__ hidden,
                          const float* __restrict__ W,
                          const float* __restrict__ bias)
{
    int row = blockIdx.x;
    int seg = blockIdx.y;
    int d   = threadIdx.x;
    __shared__ float h[DIM];
    h[d] = hidden[row * DIM + d];
    __syncthreads();
    const float* w = W + (size_t)seg * DIM * DIM + (size_t)d * DIM;
    float s = bias[seg * DIM + d];
#pragma unroll 8
    for (int e = 0; e < DIM; e++) s += h[e] * w[e];
    g_rh[(size_t)seg * BATCH * DIM + (size_t)row * DIM + d] = s;
}

__device__ __forceinline__ unsigned mono(float f) {
    unsigned u = __float_as_uint(f);
    return (u & 0x80000000u) ? ~u : (u | 0x80000000u);
}

// Suffix-scan a 4096-bin shared histogram (descending value order) and locate
// the bins + residual within-bin ranks for cutoffs 100/500/1000.
// All NTHREADS threads must call.
__device__ void suffix_find(unsigned* hist, unsigned* scanbuf, int tid,
                            int* s_bin, int* s_rank)
{
    unsigned c0 = hist[4095 - 4 * tid];
    unsigned c1 = hist[4095 - 4 * tid - 1];
    unsigned c2 = hist[4095 - 4 * tid - 2];
    unsigned c3 = hist[4095 - 4 * tid - 3];
    unsigned chunk = c0 + c1 + c2 + c3;
    scanbuf[tid] = chunk;
    __syncthreads();
    for (int off = 1; off < NTHREADS; off <<= 1) {
        unsigned v = scanbuf[tid];
        unsigned a = (tid >= off) ? scanbuf[tid - off] : 0u;
        __syncthreads();
        scanbuf[tid] = v + a;
        __syncthreads();
    }
    unsigned incl = scanbuf[tid];
    unsigned excl = incl - chunk;
    const unsigned Ks[3] = {CUT0, CUT1, CUT2};
#pragma unroll
    for (int kk = 0; kk < 3; kk++) {
        unsigned K = Ks[kk];
        if (excl < K && K <= incl) {
            unsigned c = excl;
            unsigned cc[4] = {c0, c1, c2, c3};
#pragma unroll
            for (int j = 0; j < 4; j++) {
                unsigned h = cc[j];
                if (c < K && K <= c + h) {
                    s_bin[kk]  = 4095 - 4 * tid - j;
                    s_rank[kk] = (int)(K - c);
                    break;
                }
                c += h;
            }
        }
    }
    __syncthreads();
}

// ---------------------------------------------------------------------------
// Kernel 2: one CTA per row. Single streaming pass (copy + candidate collect),
// fine-histogram threshold find, rerank dots, scatter.
// ---------------------------------------------------------------------------
__global__ void __launch_bounds__(NTHREADS)
rerank_kernel(const float* __restrict__ logits,
              const float* __restrict__ emb,
              float* __restrict__ out)
{
    __shared__ unsigned long long hot[HOTCAP];   // (mono<<32)|~idx
    __shared__ unsigned hist[NBINS];
    __shared__ unsigned scanbuf[NTHREADS];
    __shared__ float rh[NSEG * DIM];
    __shared__ unsigned long long Tkey[3];
    __shared__ int s_bin[3];
    __shared__ int s_rank[3];
    __shared__ int s_nhot;

    const int row = blockIdx.x;
    const int tid = threadIdx.x;
    const unsigned BASE = 0xC0000000u;           // mono(2.0f)

    for (int i = tid; i < NBINS; i += NTHREADS) hist[i] = 0u;
    if (tid < NSEG * DIM) {
        int seg = tid >> 7, d = tid & 127;
        rh[tid] = g_rh[(size_t)seg * BATCH * DIM + (size_t)row * DIM + d];
    }
    if (tid == 0) s_nhot = 0;
    __syncthreads();

    const float4* row4 = (const float4*)(logits + (size_t)row * VOCAB);
    float4*       out4 = (float4*)(out + (size_t)row * VOCAB);
    const int NV4 = VOCAB / 4;   // 25000

    // ------- Pass 1: stream copy + collect candidates (v > TGUESS) -------
    for (int i = tid; i < NV4; i += NTHREADS) {
        float4 v = __ldcs(&row4[i]);
        __stcs(&out4[i], v);
        bool a0 = v.x > TGUESS, a1 = v.y > TGUESS;
        bool a2 = v.z > TGUESS, a3 = v.w > TGUESS;
        if (a0 | a1 | a2 | a3) {
            int base = 4 * i;
            float vals[4] = {v.x, v.y, v.z, v.w};
            bool  act[4]  = {a0, a1, a2, a3};
#pragma unroll
            for (int j = 0; j < 4; j++) {
                if (act[j]) {
                    unsigned m = mono(vals[j]);
                    int p = atomicAdd(&s_nhot, 1);
                    if (p < HOTCAP) {
                        hot[p] = ((unsigned long long)m << 32) | (unsigned)(~(base + j));
                        unsigned fb = (m - BASE) >> 12;
                        if (fb > 4095u) fb = 4095u;
                        atomicAdd(&hist[fb], 1u);
                    }
                }
            }
        }
    }
    __syncthreads();

    int nhot = s_nhot;
    bool fast = (nhot >= CUT2) && (nhot <= HOTCAP);

    if (fast) {
        // ------- Fast path: fine-bin suffix scan over candidates only -------
        suffix_find(hist, scanbuf, tid, s_bin, s_rank);
        const int b0 = s_bin[0], b1 = s_bin[1], b2 = s_bin[2];

        for (int i = tid; i < nhot; i += NTHREADS) {
            unsigned long long k = hot[i];
            unsigned fb = ((unsigned)(k >> 32) - BASE) >> 12;
            if (fb > 4095u) fb = 4095u;
            int bin = (int)fb;
            bool m0 = (bin == b0), m1 = (bin == b1), m2 = (bin == b2);
            if (m0 | m1 | m2) {
                int cnt = 0;
                for (int j = 0; j < nhot; j++) {
                    unsigned long long kj = hot[j];
                    unsigned fbj = ((unsigned)(kj >> 32) - BASE) >> 12;
                    if (fbj > 4095u) fbj = 4095u;
                    if ((int)fbj == bin && kj > k) cnt++;
                }
                int r = cnt + 1;
                if (m0 && r == s_rank[0]) Tkey[0] = k;
                if (m1 && r == s_rank[1]) Tkey[1] = k;
                if (m2 && r == s_rank[2]) Tkey[2] = k;
            }
        }
        __syncthreads();
    } else {
        // ------- Fallback: full coarse histogram over the row (re-read) -------
        for (int i = tid; i < NBINS; i += NTHREADS) hist[i] = 0u;
        if (tid == 0) s_nhot = 0;
        __syncthreads();
        for (int i = tid; i < NV4; i += NTHREADS) {
            float4 v = row4[i];
            atomicAdd(&hist[mono(v.x) >> 20], 1u);
            atomicAdd(&hist[mono(v.y) >> 20], 1u);
            atomicAdd(&hist[mono(v.z) >> 20], 1u);
            atomicAdd(&hist[mono(v.w) >> 20], 1u);
        }
        __syncthreads();
        suffix_find(hist, scanbuf, tid, s_bin, s_rank);
        const int cb2 = s_bin[2];
        for (int i = tid; i < NV4; i += NTHREADS) {
            float4 v = row4[i];
            float vals[4] = {v.x, v.y, v.z, v.w};
            int base = 4 * i;
#pragma unroll
            for (int j = 0; j < 4; j++) {
                unsigned m = mono(vals[j]);
                if ((int)(m >> 20) >= cb2) {
                    int p = atomicAdd(&s_nhot, 1);
                    if (p < HOTCAP)
                        hot[p] = ((unsigned long long)m << 32) | (unsigned)(~(base + j));
                }
            }
        }
        __syncthreads();
        nhot = (s_nhot < HOTCAP) ? s_nhot : HOTCAP;
        const int b0 = s_bin[0], b1 = s_bin[1], b2 = s_bin[2];
        for (int i = tid; i < nhot; i += NTHREADS) {
            unsigned long long k = hot[i];
            int bin = (int)(k >> 52);
            bool m0 = (bin == b0), m1 = (bin == b1), m2 = (bin == b2);
            if (m0 | m1 | m2) {
                int cnt = 0;
                for (int j = 0; j < nhot; j++) {
                    unsigned long long kj = hot[j];
                    if ((int)(kj >> 52) == bin && kj > k) cnt++;
                }
                int r = cnt + 1;
                if (m0 && r == s_rank[0]) Tkey[0] = k;
                if (m1 && r == s_rank[1]) Tkey[1] = k;
                if (m2 && r == s_rank[2]) Tkey[2] = k;
            }
        }
        __syncthreads();
    }

    const unsigned long long T0 = Tkey[0], T1 = Tkey[1], T2 = Tkey[2];

    // ------- Dot phase: warp per surviving candidate -------
    const int wid = tid >> 5, lane = tid & 31;
    const float4* emb4 = (const float4*)emb;
    const float4* rh4  = (const float4*)rh;
    float* outrow = out + (size_t)row * VOCAB;
    for (int s = wid; s < nhot; s += (NTHREADS / 32)) {
        unsigned long long k = hot[s];
        if (k < T2) continue;
        int seg = (k >= T0) ? 0 : ((k >= T1) ? 1 : 2);
        unsigned idx = ~(unsigned)k;
        float4 e = emb4[(size_t)idx * (DIM / 4) + lane];
        float4 r = rh4[seg * (DIM / 4) + lane];
        float p = e.x * r.x + e.y * r.y + e.z * r.z + e.w * r.w;
        p += __shfl_xor_sync(0xFFFFFFFFu, p, 16);
        p += __shfl_xor_sync(0xFFFFFFFFu, p, 8);
        p += __shfl_xor_sync(0xFFFFFFFFu, p, 4);
        p += __shfl_xor_sync(0xFFFFFFFFu, p, 2);
        p += __shfl_xor_sync(0xFFFFFFFFu, p, 1);
        if (lane == 0) outrow[idx] = p;
    }
}

extern "C" void kernel_launch(void* const* d_in, const int* in_sizes, int n_in,
                              void* d_out, int out_size)
{
    const float* hidden = nullptr;
    const float* logits = nullptr;
    const float* emb    = nullptr;
    const float* W      = nullptr;
    const float* bias   = nullptr;
    for (int i = 0; i < n_in; i++) {
        switch (in_sizes[i]) {
            case BATCH * DIM:      hidden = (const float*)d_in[i]; break;
            case BATCH * VOCAB:    logits = (const float*)d_in[i]; break;
            case VOCAB * DIM:      emb    = (const float*)d_in[i]; break;
            case NSEG * DIM * DIM: W      = (const float*)d_in[i]; break;
            case NSEG * DIM:       bias   = (const float*)d_in[i]; break;
        }
    }
    float* out = (float*)d_out;

    rh_kernel<<<dim3(BATCH, NSEG), DIM>>>(hidden, W, bias);
    rerank_kernel<<<BATCH, NTHREADS>>>(logits, emb, out);
}

// round 3
// speedup vs baseline: 1.3780x; 1.1670x over previous
#include <cuda_runtime.h>
#include <cstdint>

#define BATCH    1024
#define VOCAB    100000
#define DIM      128
#define NSEG     3
#define NBINS    4096
#define HOTCAP   3072
#define NTHREADS 1024
#define CUT0 100
#define CUT1 500
#define CUT2 1000
#define TGUESS 2.0f          // rank-1000 of 100k N(0,1) ~ 2.33; P(v>2)~2.3% -> ~2275 cands

__device__ float g_rh[NSEG * BATCH * DIM];

// ---------------------------------------------------------------------------
// Kernel 1: rerank_hidden = hidden @ W[seg]^T + b[seg], tiled smem GEMM.
// grid (BATCH/32, NSEG), 256 threads. Thread (rh_half, d) computes 16 rows x 1 dim.
// ---------------------------------------------------------------------------
#define RTILE 32
#define KC 64
__global__ void __launch_bounds__(256)
rh_kernel(const float* __restrict__ hidden,
          const float* __restrict__ W,
          const float* __restrict__ bias)
{
    __shared__ float Wt[DIM][KC + 1];   // +1 pad: conflict-free column reads
    __shared__ float hs[RTILE][KC];
    const int seg = blockIdx.y;
    const int r0  = blockIdx.x * RTILE;
    const int t   = threadIdx.x;
    const int d   = t & 127;
    const int rhh = t >> 7;             // 0 or 1: which 16-row half

    float acc[16];
#pragma unroll
    for (int i = 0; i < 16; i++) acc[i] = 0.f;

    const float* Wseg = W + (size_t)seg * DIM * DIM;

    for (int kc = 0; kc < DIM; kc += KC) {
        __syncthreads();
#pragma unroll
        for (int j = 0; j < 32; j++) {          // 128x64 W tile, coalesced
            int e = t + j * 256;
            int dd = e >> 6, kk = e & 63;
            Wt[dd][kk] = Wseg[dd * DIM + kc + kk];
        }
#pragma unroll
        for (int j = 0; j < 8; j++) {           // 32x64 hidden tile, coalesced
            int e = t + j * 256;
            int rr = e >> 6, kk = e & 63;
            hs[rr][kk] = hidden[(size_t)(r0 + rr) * DIM + kc + kk];
        }
        __syncthreads();
#pragma unroll 8
        for (int k = 0; k < KC; k++) {
            float wv = Wt[d][k];                // stride-65: conflict-free
#pragma unroll
            for (int r = 0; r < 16; r++)
                acc[r] += hs[rhh * 16 + r][k] * wv;   // broadcast read
        }
    }
    float bv = bias[seg * DIM + d];
#pragma unroll
    for (int r = 0; r < 16; r++) {
        int row = r0 + rhh * 16 + r;
        g_rh[(size_t)seg * BATCH * DIM + (size_t)row * DIM + d] = acc[r] + bv;
    }
}

__device__ __forceinline__ unsigned mono(float f) {
    unsigned u = __float_as_uint(f);
    return (u & 0x80000000u) ? ~u : (u | 0x80000000u);
}

// Suffix-scan 4096-bin histogram (descending), find bins + residual ranks.
__device__ void suffix_find(unsigned* hist, unsigned* scanbuf, int tid,
                            int* s_bin, int* s_rank)
{
    unsigned c0 = hist[4095 - 4 * tid];
    unsigned c1 = hist[4095 - 4 * tid - 1];
    unsigned c2 = hist[4095 - 4 * tid - 2];
    unsigned c3 = hist[4095 - 4 * tid - 3];
    unsigned chunk = c0 + c1 + c2 + c3;
    scanbuf[tid] = chunk;
    __syncthreads();
    for (int off = 1; off < NTHREADS; off <<= 1) {
        unsigned v = scanbuf[tid];
        unsigned a = (tid >= off) ? scanbuf[tid - off] : 0u;
        __syncthreads();
        scanbuf[tid] = v + a;
        __syncthreads();
    }
    unsigned incl = scanbuf[tid];
    unsigned excl = incl - chunk;
    const unsigned Ks[3] = {CUT0, CUT1, CUT2};
#pragma unroll
    for (int kk = 0; kk < 3; kk++) {
        unsigned K = Ks[kk];
        if (excl < K && K <= incl) {
            unsigned c = excl;
            unsigned cc[4] = {c0, c1, c2, c3};
#pragma unroll
            for (int j = 0; j < 4; j++) {
                unsigned h = cc[j];
                if (c < K && K <= c + h) {
                    s_bin[kk]  = 4095 - 4 * tid - j;
                    s_rank[kk] = (int)(K - c);
                    break;
                }
                c += h;
            }
        }
    }
    __syncthreads();
}

// ---------------------------------------------------------------------------
// Kernel 2: one CTA per row.
// ---------------------------------------------------------------------------
__global__ void __launch_bounds__(NTHREADS)
rerank_kernel(const float* __restrict__ logits,
              const float* __restrict__ emb,
              float* __restrict__ out)
{
    __shared__ unsigned long long hot[HOTCAP];
    __shared__ unsigned hist[NBINS];
    __shared__ unsigned scanbuf[NTHREADS];
    __shared__ float rh[NSEG * DIM];
    __shared__ unsigned long long Tkey[3];
    __shared__ int s_bin[3];
    __shared__ int s_rank[3];
    __shared__ int s_nhot;

    const int row = blockIdx.x;
    const int tid = threadIdx.x;
    const unsigned BASE = 0xC0000000u;           // mono(2.0f)

    for (int i = tid; i < NBINS; i += NTHREADS) hist[i] = 0u;
    if (tid < NSEG * DIM) {
        int seg = tid >> 7, d = tid & 127;
        rh[tid] = g_rh[(size_t)seg * BATCH * DIM + (size_t)row * DIM + d];
    }
    if (tid == 0) s_nhot = 0;
    __syncthreads();

    const float4* row4 = (const float4*)(logits + (size_t)row * VOCAB);
    float4*       out4 = (float4*)(out + (size_t)row * VOCAB);
    const int NV4 = VOCAB / 4;   // 25000

    // ------- Pass 1: 4-way batched stream copy + candidate collect -------
    for (int base = 0; base < NV4; base += NTHREADS * 4) {
        float4 v[4];
        int ii[4];
        bool ok[4];
#pragma unroll
        for (int j = 0; j < 4; j++) {                 // batched loads: MLP >= 4
            ii[j] = base + j * NTHREADS + tid;
            ok[j] = ii[j] < NV4;
            if (ok[j]) v[j] = __ldcs(&row4[ii[j]]);
        }
#pragma unroll
        for (int j = 0; j < 4; j++)
            if (ok[j]) __stcs(&out4[ii[j]], v[j]);
#pragma unroll
        for (int j = 0; j < 4; j++) {
            if (!ok[j]) continue;
            float4 vv = v[j];
            bool a0 = vv.x > TGUESS, a1 = vv.y > TGUESS;
            bool a2 = vv.z > TGUESS, a3 = vv.w > TGUESS;
            if (a0 | a1 | a2 | a3) {
                int b4 = 4 * ii[j];
                float vals[4] = {vv.x, vv.y, vv.z, vv.w};
                bool  act[4]  = {a0, a1, a2, a3};
#pragma unroll
                for (int q = 0; q < 4; q++) {
                    if (act[q]) {
                        unsigned m = mono(vals[q]);
                        int p = atomicAdd(&s_nhot, 1);
                        if (p < HOTCAP) {
                            hot[p] = ((unsigned long long)m << 32) | (unsigned)(~(b4 + q));
                            unsigned fb = (m - BASE) >> 12;
                            if (fb > 4095u) fb = 4095u;
                            atomicAdd(&hist[fb], 1u);
                        }
                    }
                }
            }
        }
    }
    __syncthreads();

    int nhot = s_nhot;
    bool fast = (nhot >= CUT2) && (nhot <= HOTCAP);

    if (fast) {
        suffix_find(hist, scanbuf, tid, s_bin, s_rank);
        const int b0 = s_bin[0], b1 = s_bin[1], b2 = s_bin[2];
        for (int i = tid; i < nhot; i += NTHREADS) {
            unsigned long long k = hot[i];
            unsigned fb = ((unsigned)(k >> 32) - BASE) >> 12;
            if (fb > 4095u) fb = 4095u;
            int bin = (int)fb;
            bool m0 = (bin == b0), m1 = (bin == b1), m2 = (bin == b2);
            if (m0 | m1 | m2) {
                int cnt = 0;
                for (int j = 0; j < nhot; j++) {
                    unsigned long long kj = hot[j];
                    unsigned fbj = ((unsigned)(kj >> 32) - BASE) >> 12;
                    if (fbj > 4095u) fbj = 4095u;
                    if ((int)fbj == bin && kj > k) cnt++;
                }
                int r = cnt + 1;
                if (m0 && r == s_rank[0]) Tkey[0] = k;
                if (m1 && r == s_rank[1]) Tkey[1] = k;
                if (m2 && r == s_rank[2]) Tkey[2] = k;
            }
        }
        __syncthreads();
    } else {
        // ------- Fallback: full coarse histogram over the row -------
        for (int i = tid; i < NBINS; i += NTHREADS) hist[i] = 0u;
        if (tid == 0) s_nhot = 0;
        __syncthreads();
        for (int i = tid; i < NV4; i += NTHREADS) {
            float4 v = row4[i];
            atomicAdd(&hist[mono(v.x) >> 20], 1u);
            atomicAdd(&hist[mono(v.y) >> 20], 1u);
            atomicAdd(&hist[mono(v.z) >> 20], 1u);
            atomicAdd(&hist[mono(v.w) >> 20], 1u);
        }
        __syncthreads();
        suffix_find(hist, scanbuf, tid, s_bin, s_rank);
        const int cb2 = s_bin[2];
        for (int i = tid; i < NV4; i += NTHREADS) {
            float4 v = row4[i];
            float vals[4] = {v.x, v.y, v.z, v.w};
            int b4 = 4 * i;
#pragma unroll
            for (int j = 0; j < 4; j++) {
                unsigned m = mono(vals[j]);
                if ((int)(m >> 20) >= cb2) {
                    int p = atomicAdd(&s_nhot, 1);
                    if (p < HOTCAP)
                        hot[p] = ((unsigned long long)m << 32) | (unsigned)(~(b4 + j));
                }
            }
        }
        __syncthreads();
        nhot = (s_nhot < HOTCAP) ? s_nhot : HOTCAP;
        const int b0 = s_bin[0], b1 = s_bin[1], b2 = s_bin[2];
        for (int i = tid; i < nhot; i += NTHREADS) {
            unsigned long long k = hot[i];
            int bin = (int)(k >> 52);
            bool m0 = (bin == b0), m1 = (bin == b1), m2 = (bin == b2);
            if (m0 | m1 | m2) {
                int cnt = 0;
                for (int j = 0; j < nhot; j++) {
                    unsigned long long kj = hot[j];
                    if ((int)(kj >> 52) == bin && kj > k) cnt++;
                }
                int r = cnt + 1;
                if (m0 && r == s_rank[0]) Tkey[0] = k;
                if (m1 && r == s_rank[1]) Tkey[1] = k;
                if (m2 && r == s_rank[2]) Tkey[2] = k;
            }
        }
        __syncthreads();
    }

    const unsigned long long T0 = Tkey[0], T1 = Tkey[1], T2 = Tkey[2];

    // ------- Dot phase: 4 candidates per warp per round (MLP 4) -------
    const int wid = tid >> 5, lane = tid & 31;
    const int NW = NTHREADS / 32;
    const float4* emb4 = (const float4*)emb;
    const float4* rh4  = (const float4*)rh;
    float* outrow = out + (size_t)row * VOCAB;

    for (int s = wid * 4; s < nhot; s += NW * 4) {
        unsigned long long k[4];
        bool act[4];
        unsigned idx[4];
        float4 e[4], r[4];
#pragma unroll
        for (int j = 0; j < 4; j++) {
            int si = s + j;
            k[j] = (si < nhot) ? hot[si] : 0ull;
            act[j] = (k[j] >= T2);
            if (act[j]) {
                int seg = (k[j] >= T0) ? 0 : ((k[j] >= T1) ? 1 : 2);
                idx[j] = ~(unsigned)k[j];
                e[j] = emb4[(size_t)idx[j] * (DIM / 4) + lane];   // batched gathers
                r[j] = rh4[seg * (DIM / 4) + lane];
            }
        }
#pragma unroll
        for (int j = 0; j < 4; j++) {
            if (!act[j]) continue;
            float p = e[j].x * r[j].x + e[j].y * r[j].y + e[j].z * r[j].z + e[j].w * r[j].w;
            p += __shfl_xor_sync(0xFFFFFFFFu, p, 16);
            p += __shfl_xor_sync(0xFFFFFFFFu, p, 8);
            p += __shfl_xor_sync(0xFFFFFFFFu, p, 4);
            p += __shfl_xor_sync(0xFFFFFFFFu, p, 2);
            p += __shfl_xor_sync(0xFFFFFFFFu, p, 1);
            if (lane == 0) outrow[idx[j]] = p;
        }
    }
}

extern "C" void kernel_launch(void* const* d_in, const int* in_sizes, int n_in,
                              void* d_out, int out_size)
{
    const float* hidden = nullptr;
    const float* logits = nullptr;
    const float* emb    = nullptr;
    const float* W      = nullptr;
    const float* bias   = nullptr;
    for (int i = 0; i < n_in; i++) {
        switch (in_sizes[i]) {
            case BATCH * DIM:      hidden = (const float*)d_in[i]; break;
            case BATCH * VOCAB:    logits = (const float*)d_in[i]; break;
            case VOCAB * DIM:      emb    = (const float*)d_in[i]; break;
            case NSEG * DIM * DIM: W      = (const float*)d_in[i]; break;
            case NSEG * DIM:       bias   = (const float*)d_in[i]; break;
        }
    }
    float* out = (float*)d_out;

    rh_kernel<<<dim3(BATCH / RTILE, NSEG), 256>>>(hidden, W, bias);
    rerank_kernel<<<BATCH, NTHREADS>>>(logits, emb, out);
}

// round 4
// speedup vs baseline: 1.4692x; 1.0661x over previous
#include <cuda_runtime.h>
#include <cstdint>

#define BATCH    1024
#define VOCAB    100000
#define DIM      128
#define NSEG     3
#define NBINS    4096
#define HOTCAP   3072
#define NTHREADS 512
#define CUT0 100
#define CUT1 500
#define CUT2 1000
#define TGUESS 2.0f          // rank-1000 of 100k N(0,1) ~ 2.33; P(v>2)~2.3% -> ~2275 cands

__device__ float g_rh[NSEG * BATCH * DIM];

// ---------------------------------------------------------------------------
// Kernel 1: rerank_hidden = hidden @ W[seg]^T + b[seg], tiled smem GEMM.
// ---------------------------------------------------------------------------
#define RTILE 32
#define KC 64
__global__ void __launch_bounds__(256)
rh_kernel(const float* __restrict__ hidden,
          const float* __restrict__ W,
          const float* __restrict__ bias)
{
    __shared__ float Wt[DIM][KC + 1];
    __shared__ float hs[RTILE][KC];
    const int seg = blockIdx.y;
    const int r0  = blockIdx.x * RTILE;
    const int t   = threadIdx.x;
    const int d   = t & 127;
    const int rhh = t >> 7;

    float acc[16];
#pragma unroll
    for (int i = 0; i < 16; i++) acc[i] = 0.f;

    const float* Wseg = W + (size_t)seg * DIM * DIM;

    for (int kc = 0; kc < DIM; kc += KC) {
        __syncthreads();
#pragma unroll
        for (int j = 0; j < 32; j++) {
            int e = t + j * 256;
            int dd = e >> 6, kk = e & 63;
            Wt[dd][kk] = Wseg[dd * DIM + kc + kk];
        }
#pragma unroll
        for (int j = 0; j < 8; j++) {
            int e = t + j * 256;
            int rr = e >> 6, kk = e & 63;
            hs[rr][kk] = hidden[(size_t)(r0 + rr) * DIM + kc + kk];
        }
        __syncthreads();
#pragma unroll 8
        for (int k = 0; k < KC; k++) {
            float wv = Wt[d][k];
#pragma unroll
            for (int r = 0; r < 16; r++)
                acc[r] += hs[rhh * 16 + r][k] * wv;
        }
    }
    float bv = bias[seg * DIM + d];
#pragma unroll
    for (int r = 0; r < 16; r++) {
        int row = r0 + rhh * 16 + r;
        g_rh[(size_t)seg * BATCH * DIM + (size_t)row * DIM + d] = acc[r] + bv;
    }
}

__device__ __forceinline__ unsigned mono(float f) {
    unsigned u = __float_as_uint(f);
    return (u & 0x80000000u) ? ~u : (u | 0x80000000u);
}

// ---------------------------------------------------------------------------
// Scan 4096-bin histogram in descending-value order with shfl (2 barriers).
// Thread t owns bins [4095-8t .. 4095-8t-7]. Finds cutoff bins + ranks.
// ---------------------------------------------------------------------------
__device__ void scan_find(unsigned* hist, unsigned* warpsum, int tid,
                          int* s_bin, int* s_rank)
{
    const int lane = tid & 31, w = tid >> 5;
    unsigned c[8];
    unsigned chunk = 0;
#pragma unroll
    for (int j = 0; j < 8; j++) {
        c[j] = hist[4095 - 8 * tid - j];
        chunk += c[j];
    }
    unsigned pfx = chunk;                           // inclusive warp scan
#pragma unroll
    for (int off = 1; off < 32; off <<= 1) {
        unsigned n = __shfl_up_sync(0xFFFFFFFFu, pfx, off);
        if (lane >= off) pfx += n;
    }
    if (lane == 31) warpsum[w] = pfx;
    __syncthreads();
    if (w == 0) {
        unsigned s = (lane < 16) ? warpsum[lane] : 0u;
#pragma unroll
        for (int off = 1; off < 16; off <<= 1) {
            unsigned n = __shfl_up_sync(0xFFFFFFFFu, s, off);
            if (lane >= off) s += n;
        }
        if (lane < 16) warpsum[lane] = s;           // inclusive warp totals
    }
    __syncthreads();
    unsigned wbase = (w > 0) ? warpsum[w - 1] : 0u;
    unsigned incl = wbase + pfx;
    unsigned excl = incl - chunk;
    const unsigned Ks[3] = {CUT0, CUT1, CUT2};
#pragma unroll
    for (int kk = 0; kk < 3; kk++) {
        unsigned K = Ks[kk];
        if (excl < K && K <= incl) {
            unsigned cc = excl;
#pragma unroll
            for (int j = 0; j < 8; j++) {
                unsigned h = c[j];
                if (cc < K && K <= cc + h) {
                    s_bin[kk]  = 4095 - 8 * tid - j;
                    s_rank[kk] = (int)(K - cc);
                    break;
                }
                cc += h;
            }
        }
    }
    __syncthreads();
}

// ---------------------------------------------------------------------------
// Kernel 2: one CTA (512 thr) per row; 4 CTAs/SM.
// ---------------------------------------------------------------------------
__global__ void __launch_bounds__(NTHREADS, 4)
rerank_kernel(const float* __restrict__ logits,
              const float* __restrict__ emb,
              float* __restrict__ out)
{
    __shared__ unsigned long long hot[HOTCAP];
    __shared__ unsigned hist[NBINS];
    __shared__ unsigned warpsum[16];
    __shared__ float rh[NSEG * DIM];
    __shared__ unsigned long long Tkey[3];
    __shared__ int s_bin[3];
    __shared__ int s_rank[3];
    __shared__ int s_nhot;

    const int row = blockIdx.x;
    const int tid = threadIdx.x;
    const int lane = tid & 31;
    const unsigned BASE = 0xC0000000u;           // mono(2.0f)

    for (int i = tid; i < NBINS; i += NTHREADS) hist[i] = 0u;
    if (tid < NSEG * DIM) {
        int seg = tid >> 7, d = tid & 127;
        rh[tid] = g_rh[(size_t)seg * BATCH * DIM + (size_t)row * DIM + d];
    }
    if (tid == 0) s_nhot = 0;
    __syncthreads();

    const float4* row4 = (const float4*)(logits + (size_t)row * VOCAB);
    float4*       out4 = (float4*)(out + (size_t)row * VOCAB);
    const int NV4 = VOCAB / 4;   // 25000

    // ------- Pass 1: 2-way batched stream copy + warp-aggregated collect -----
    for (int base = 0; base < NV4; base += NTHREADS * 2) {
        int i0 = base + tid;
        int i1 = base + NTHREADS + tid;
        bool ok0 = i0 < NV4, ok1 = i1 < NV4;
        float4 v0, v1;
        if (ok0) v0 = __ldcs(&row4[i0]);
        if (ok1) v1 = __ldcs(&row4[i1]);
        if (ok0) __stcs(&out4[i0], v0);
        if (ok1) __stcs(&out4[i1], v1);

        int cnt = 0;
        if (ok0) cnt += (v0.x > TGUESS) + (v0.y > TGUESS) + (v0.z > TGUESS) + (v0.w > TGUESS);
        if (ok1) cnt += (v1.x > TGUESS) + (v1.y > TGUESS) + (v1.z > TGUESS) + (v1.w > TGUESS);

        unsigned anyb = __ballot_sync(0xFFFFFFFFu, cnt > 0);
        if (anyb) {
            // warp-exclusive prefix of cnt, single shared atomic per warp
            int pfx = cnt;
#pragma unroll
            for (int off = 1; off < 32; off <<= 1) {
                int n = __shfl_up_sync(0xFFFFFFFFu, pfx, off);
                if (lane >= off) pfx += n;
            }
            int total = __shfl_sync(0xFFFFFFFFu, pfx, 31);
            int wbase = 0;
            if (lane == 31) wbase = atomicAdd(&s_nhot, total);
            wbase = __shfl_sync(0xFFFFFFFFu, wbase, 31);
            int slot = wbase + pfx - cnt;
            if (cnt) {
                float vals[8] = {v0.x, v0.y, v0.z, v0.w, v1.x, v1.y, v1.z, v1.w};
                int   idxs[8] = {4*i0, 4*i0+1, 4*i0+2, 4*i0+3,
                                 4*i1, 4*i1+1, 4*i1+2, 4*i1+3};
                bool  oks[8]  = {ok0, ok0, ok0, ok0, ok1, ok1, ok1, ok1};
#pragma unroll
                for (int j = 0; j < 8; j++) {
                    if (oks[j] && vals[j] > TGUESS) {
                        unsigned m = mono(vals[j]);
                        if (slot < HOTCAP) {
                            hot[slot] = ((unsigned long long)m << 32) | (unsigned)(~idxs[j]);
                            unsigned fb = (m - BASE) >> 12;
                            if (fb > 4095u) fb = 4095u;
                            atomicAdd(&hist[fb], 1u);
                        }
                        slot++;
                    }
                }
            }
        }
    }
    __syncthreads();

    int nhot = s_nhot;
    bool fast = (nhot >= CUT2) && (nhot <= HOTCAP);

    if (fast) {
        scan_find(hist, warpsum, tid, s_bin, s_rank);
        const int b0 = s_bin[0], b1 = s_bin[1], b2 = s_bin[2];
        for (int i = tid; i < nhot; i += NTHREADS) {
            unsigned long long k = hot[i];
            unsigned fb = ((unsigned)(k >> 32) - BASE) >> 12;
            if (fb > 4095u) fb = 4095u;
            int bin = (int)fb;
            bool m0 = (bin == b0), m1 = (bin == b1), m2 = (bin == b2);
            if (m0 | m1 | m2) {
                int cnt = 0;
                for (int j = 0; j < nhot; j++) {
                    unsigned long long kj = hot[j];
                    unsigned fbj = ((unsigned)(kj >> 32) - BASE) >> 12;
                    if (fbj > 4095u) fbj = 4095u;
                    if ((int)fbj == bin && kj > k) cnt++;
                }
                int r = cnt + 1;
                if (m0 && r == s_rank[0]) Tkey[0] = k;
                if (m1 && r == s_rank[1]) Tkey[1] = k;
                if (m2 && r == s_rank[2]) Tkey[2] = k;
            }
        }
        __syncthreads();
    } else {
        // ------- Fallback: full coarse histogram over the row -------
        for (int i = tid; i < NBINS; i += NTHREADS) hist[i] = 0u;
        if (tid == 0) s_nhot = 0;
        __syncthreads();
        for (int i = tid; i < NV4; i += NTHREADS) {
            float4 v = row4[i];
            atomicAdd(&hist[mono(v.x) >> 20], 1u);
            atomicAdd(&hist[mono(v.y) >> 20], 1u);
            atomicAdd(&hist[mono(v.z) >> 20], 1u);
            atomicAdd(&hist[mono(v.w) >> 20], 1u);
        }
        __syncthreads();
        scan_find(hist, warpsum, tid, s_bin, s_rank);
        const int cb2 = s_bin[2];
        for (int i = tid; i < NV4; i += NTHREADS) {
            float4 v = row4[i];
            float vals[4] = {v.x, v.y, v.z, v.w};
            int b4 = 4 * i;
#pragma unroll
            for (int j = 0; j < 4; j++) {
                unsigned m = mono(vals[j]);
                if ((int)(m >> 20) >= cb2) {
                    int p = atomicAdd(&s_nhot, 1);
                    if (p < HOTCAP)
                        hot[p] = ((unsigned long long)m << 32) | (unsigned)(~(b4 + j));
                }
            }
        }
        __syncthreads();
        nhot = (s_nhot < HOTCAP) ? s_nhot : HOTCAP;
        const int b0 = s_bin[0], b1 = s_bin[1], b2 = s_bin[2];
        for (int i = tid; i < nhot; i += NTHREADS) {
            unsigned long long k = hot[i];
            int bin = (int)(k >> 52);
            bool m0 = (bin == b0), m1 = (bin == b1), m2 = (bin == b2);
            if (m0 | m1 | m2) {
                int cnt = 0;
                for (int j = 0; j < nhot; j++) {
                    unsigned long long kj = hot[j];
                    if ((int)(kj >> 52) == bin && kj > k) cnt++;
                }
                int r = cnt + 1;
                if (m0 && r == s_rank[0]) Tkey[0] = k;
                if (m1 && r == s_rank[1]) Tkey[1] = k;
                if (m2 && r == s_rank[2]) Tkey[2] = k;
            }
        }
        __syncthreads();
    }

    const unsigned long long T0 = Tkey[0], T1 = Tkey[1], T2 = Tkey[2];

    // ------- Dot phase: 2 candidates per warp per round -------
    const int wid = tid >> 5;
    const int NW = NTHREADS / 32;
    const float4* emb4 = (const float4*)emb;
    const float4* rh4  = (const float4*)rh;
    float* outrow = out + (size_t)row * VOCAB;

    for (int s = wid * 2; s < nhot; s += NW * 2) {
        unsigned long long k[2];
        bool act[2];
        unsigned idx[2];
        float4 e[2];
        int seg[2];
#pragma unroll
        for (int j = 0; j < 2; j++) {
            int si = s + j;
            k[j] = (si < nhot) ? hot[si] : 0ull;
            act[j] = (k[j] >= T2);
            if (act[j]) {
                seg[j] = (k[j] >= T0) ? 0 : ((k[j] >= T1) ? 1 : 2);
                idx[j] = ~(unsigned)k[j];
                e[j] = emb4[(size_t)idx[j] * (DIM / 4) + lane];
            }
        }
#pragma unroll
        for (int j = 0; j < 2; j++) {
            if (!act[j]) continue;
            float4 r = rh4[seg[j] * (DIM / 4) + lane];
            float p = e[j].x * r.x + e[j].y * r.y + e[j].z * r.z + e[j].w * r.w;
            p += __shfl_xor_sync(0xFFFFFFFFu, p, 16);
            p += __shfl_xor_sync(0xFFFFFFFFu, p, 8);
            p += __shfl_xor_sync(0xFFFFFFFFu, p, 4);
            p += __shfl_xor_sync(0xFFFFFFFFu, p, 2);
            p += __shfl_xor_sync(0xFFFFFFFFu, p, 1);
            if (lane == 0) outrow[idx[j]] = p;
        }
    }
}

extern "C" void kernel_launch(void* const* d_in, const int* in_sizes, int n_in,
                              void* d_out, int out_size)
{
    const float* hidden = nullptr;
    const float* logits = nullptr;
    const float* emb    = nullptr;
    const float* W      = nullptr;
    const float* bias   = nullptr;
    for (int i = 0; i < n_in; i++) {
        switch (in_sizes[i]) {
            case BATCH * DIM:      hidden = (const float*)d_in[i]; break;
            case BATCH * VOCAB:    logits = (const float*)d_in[i]; break;
            case VOCAB * DIM:      emb    = (const float*)d_in[i]; break;
            case NSEG * DIM * DIM: W      = (const float*)d_in[i]; break;
            case NSEG * DIM:       bias   = (const float*)d_in[i]; break;
        }
    }
    float* out = (float*)d_out;

    rh_kernel<<<dim3(BATCH / RTILE, NSEG), 256>>>(hidden, W, bias);
    rerank_kernel<<<BATCH, NTHREADS>>>(logits, emb, out);
}